// round 12
// baseline (speedup 1.0000x reference)
#include <cuda_runtime.h>
#include <cuda_bf16.h>
#include <mma.h>
#include <cstdint>

using namespace nvcuda;

#define MAXN 100000
#define MAXE 1600000

// ---------------- static scratch (allocation-free rule) ----------------
__device__ __align__(16) int   g_cnt[MAXN];      // in-degree (excl. self loop)
__device__ __align__(16) int   g_cur[MAXN];      // fill cursors
__device__ __align__(16) int   g_rowptr[MAXN];   // CSR row starts
__device__ __align__(16) int   g_bsum[512];      // block sums for scan
__device__ __align__(16) float g_dinv[MAXN];
__device__ __align__(16) int2  g_csr[MAXE];      // (src, bitcast norm)
__device__ __align__(16) float g_xwA[MAXN * 32];
__device__ __align__(16) float g_xwB[MAXN * 32];
// bf16 hi/lo planes for MLP inputs (split-precision tensor GEMM)
__device__ __align__(16) __nv_bfloat16 g_fh[(size_t)MAXN * 192];
__device__ __align__(16) __nv_bfloat16 g_fl[(size_t)MAXN * 192];
__device__ __align__(16) __nv_bfloat16 g_h1h[(size_t)MAXN * 256];
__device__ __align__(16) __nv_bfloat16 g_h1l[(size_t)MAXN * 256];
__device__ __align__(16) float g_h2[(size_t)MAXN * 256];
// weights transposed to [N][K] bf16 hi/lo
__device__ __align__(16) __nv_bfloat16 g_B1h[192 * 256];
__device__ __align__(16) __nv_bfloat16 g_B1l[192 * 256];
__device__ __align__(16) __nv_bfloat16 g_B2h[256 * 256];
__device__ __align__(16) __nv_bfloat16 g_B2l[256 * 256];
__device__ __align__(16) float g_conc[MAXN];
__device__ float g_partial[512];
__device__ float g_sum;

// bf16 hi/lo split
__device__ __forceinline__ void bsplit(float v, __nv_bfloat16& h, __nv_bfloat16& l) {
    h = __float2bfloat16(v);
    l = __float2bfloat16(v - __bfloat162float(h));
}

// ---------------- CSR build ----------------
__global__ void __launch_bounds__(256) k_prep(int Nn) {
    int i = blockIdx.x * blockDim.x + threadIdx.x;
    if (i < Nn) { g_cnt[i] = 0; g_cur[i] = 0; }
    if (i == 0) g_sum = 0.0f;
}
__global__ void __launch_bounds__(256) k_cnt(const int* __restrict__ dst, int E) {
    int e = blockIdx.x * blockDim.x + threadIdx.x;
    if (e < E) atomicAdd(&g_cnt[dst[e]], 1);
}
// per-block sums of g_cnt (256 per block)
__global__ void __launch_bounds__(256) k_scanA(int Nn) {
    __shared__ int sh[256];
    int i = blockIdx.x * 256 + threadIdx.x;
    sh[threadIdx.x] = (i < Nn) ? g_cnt[i] : 0;
    __syncthreads();
    for (int o = 128; o; o >>= 1) {
        if (threadIdx.x < o) sh[threadIdx.x] += sh[threadIdx.x + o];
        __syncthreads();
    }
    if (threadIdx.x == 0) g_bsum[blockIdx.x] = sh[0];
}
// exclusive scan of block sums (nb <= 512), one block of 512
__global__ void __launch_bounds__(512) k_scanB(int nb) {
    __shared__ int sh[512];
    int t = threadIdx.x;
    int v = (t < nb) ? g_bsum[t] : 0;
    sh[t] = v;
    __syncthreads();
    for (int o = 1; o < 512; o <<= 1) {
        int x = (t >= o) ? sh[t - o] : 0;
        __syncthreads();
        sh[t] += x;
        __syncthreads();
    }
    if (t < nb) g_bsum[t] = sh[t] - v;   // exclusive
}
// local exclusive scan + block offset -> rowptr; also dinv
__global__ void __launch_bounds__(256) k_scanC(int Nn) {
    __shared__ int sh[256];
    int i = blockIdx.x * 256 + threadIdx.x;
    int t = threadIdx.x;
    int v = (i < Nn) ? g_cnt[i] : 0;
    sh[t] = v;
    __syncthreads();
    for (int o = 1; o < 256; o <<= 1) {
        int x = (t >= o) ? sh[t - o] : 0;
        __syncthreads();
        sh[t] += x;
        __syncthreads();
    }
    if (i < Nn) {
        g_rowptr[i] = g_bsum[blockIdx.x] + sh[t] - v;
        g_dinv[i] = rsqrtf((float)(v + 1));   // + self loop
    }
}
__global__ void __launch_bounds__(256) k_fill(const int* __restrict__ src,
                                              const int* __restrict__ dst, int E) {
    int e = blockIdx.x * blockDim.x + threadIdx.x;
    if (e >= E) return;
    int s = src[e], d = dst[e];
    int pos = g_rowptr[d] + atomicAdd(&g_cur[d], 1);
    float w = g_dinv[s] * g_dinv[d];
    g_csr[pos] = make_int2(s, __float_as_int(w));
}

// ---------------- layer 1 front: xw1 = state @ W1; store state -> feat 160..191 ----
__global__ void __launch_bounds__(256) k_xw0(const float* __restrict__ state,
                                             const float* __restrict__ W, int Nn) {
    __shared__ float Ws[1024];
    int tid = threadIdx.x;
    for (int i = tid; i < 1024; i += 256) Ws[i] = W[i];
    __syncthreads();
    int lane = tid & 31;
    int node = blockIdx.x * 8 + (tid >> 5);
    if (node >= Nn) return;
    float v = state[node * 32 + lane];
    __nv_bfloat16 h, l;
    bsplit(v, h, l);
    size_t o = (size_t)node * 192 + 160 + lane;
    g_fh[o] = h;
    g_fl[o] = l;
    float acc = 0.0f;
#pragma unroll
    for (int k = 0; k < 32; k++) {
        float xk = __shfl_sync(0xffffffffu, v, k);
        acc = fmaf(xk, Ws[k * 32 + lane], acc);
    }
    g_xwA[node * 32 + lane] = acc;
}

// ---------------- fused pull layer: agg -> relu -> feat store -> next xw ----------
// PP=0: in g_xwA, out g_xwB ; PP=1: in g_xwB, out g_xwA
// Edge loop software-pipelined x4: batch CSR loads, then batch gathers (MLP>=4).
template <int FCOL, int HASNEXT, int PP>
__global__ void __launch_bounds__(256) k_pull(const float* __restrict__ b_cur,
                                              const float* __restrict__ Wnext, int Nn) {
    const float* __restrict__ xw_in = PP ? g_xwB : g_xwA;
    float* __restrict__ xw_out      = PP ? g_xwA : g_xwB;
    __shared__ float Ws[1024];
    int tid = threadIdx.x;
    if (HASNEXT) {
        for (int i = tid; i < 1024; i += 256) Ws[i] = Wnext[i];
        __syncthreads();
    }
    int lane = tid & 31;
    int node = blockIdx.x * 8 + (tid >> 5);
    if (node >= Nn) return;

    float di = g_dinv[node];
    float acc = di * di * xw_in[node * 32 + lane] + b_cur[lane];
    int start = g_rowptr[node];
    int cnt = g_cnt[node];
    int i = start;
    int end4 = start + (cnt & ~3);
    for (; i < end4; i += 4) {
        int2 p0 = g_csr[i];
        int2 p1 = g_csr[i + 1];
        int2 p2 = g_csr[i + 2];
        int2 p3 = g_csr[i + 3];
        float x0 = xw_in[(size_t)p0.x * 32 + lane];
        float x1 = xw_in[(size_t)p1.x * 32 + lane];
        float x2 = xw_in[(size_t)p2.x * 32 + lane];
        float x3 = xw_in[(size_t)p3.x * 32 + lane];
        acc = fmaf(__int_as_float(p0.y), x0, acc);
        acc = fmaf(__int_as_float(p1.y), x1, acc);
        acc = fmaf(__int_as_float(p2.y), x2, acc);
        acc = fmaf(__int_as_float(p3.y), x3, acc);
    }
    int end = start + cnt;
    for (; i < end; i++) {
        int2 p = g_csr[i];
        acc = fmaf(__int_as_float(p.y), xw_in[(size_t)p.x * 32 + lane], acc);
    }
    float v = fmaxf(acc, 0.0f);
    __nv_bfloat16 h, l;
    bsplit(v, h, l);
    size_t o = (size_t)node * 192 + FCOL + lane;
    g_fh[o] = h;
    g_fl[o] = l;
    if (HASNEXT) {
        float a2 = 0.0f;
#pragma unroll
        for (int k = 0; k < 32; k++) {
            float xk = __shfl_sync(0xffffffffu, v, k);
            a2 = fmaf(xk, Ws[k * 32 + lane], a2);
        }
        xw_out[node * 32 + lane] = a2;
    }
}

// ---------------- weight convert + transpose: W[K][256] -> [N][K] bf16 hi/lo ----
template <int K, int WHICH>
__global__ void __launch_bounds__(256) k_convB(const float* __restrict__ Wt) {
    int idx = blockIdx.x * blockDim.x + threadIdx.x;
    if (idx >= K * 256) return;
    int k = idx >> 8, n = idx & 255;
    __nv_bfloat16 h, l;
    bsplit(Wt[idx], h, l);
    if (WHICH == 0) { g_B1h[n * K + k] = h; g_B1l[n * K + k] = l; }
    else           { g_B2h[n * K + k] = h; g_B2l[n * K + k] = l; }
}

// ---------------- wmma bf16x3 split GEMM (identical to R6/R10 pass) ----------------
template <int KTOT, int SRC>
__global__ void __launch_bounds__(256) k_gemm_mma(const float* __restrict__ bias, int Nn) {
    extern __shared__ char sm[];
    const int LDT = 40;
    __nv_bfloat16* Ah = (__nv_bfloat16*)(sm);
    __nv_bfloat16* Al = (__nv_bfloat16*)(sm + 10240);
    __nv_bfloat16* Bh = (__nv_bfloat16*)(sm + 20480);
    __nv_bfloat16* Bl = (__nv_bfloat16*)(sm + 30720);

    int tid = threadIdx.x;
    int wid = tid >> 5, lane = tid & 31;
    int wm = wid & 3, wn = wid >> 2;
    int m0 = blockIdx.x * 128;
    int n0 = blockIdx.y * 128;

    const __nv_bfloat16* gAh = (SRC == 0) ? g_fh : g_h1h;
    const __nv_bfloat16* gAl = (SRC == 0) ? g_fl : g_h1l;
    const __nv_bfloat16* gBh = (SRC == 0) ? g_B1h : g_B2h;
    const __nv_bfloat16* gBl = (SRC == 0) ? g_B1l : g_B2l;

    wmma::fragment<wmma::accumulator, 16, 16, 16, float> acc[2][4];
#pragma unroll
    for (int i = 0; i < 2; i++)
#pragma unroll
        for (int j = 0; j < 4; j++) wmma::fill_fragment(acc[i][j], 0.0f);

    for (int k0 = 0; k0 < KTOT; k0 += 32) {
#pragma unroll
        for (int u = 0; u < 4; u++) {
            int idx = tid + u * 256;
            int r = idx >> 3, c = idx & 7;
            int gm = m0 + r;
            unsigned long long vh = 0ull, vl = 0ull;
            if (gm < Nn) {
                vh = *(const unsigned long long*)(gAh + (size_t)gm * KTOT + k0 + c * 4);
                vl = *(const unsigned long long*)(gAl + (size_t)gm * KTOT + k0 + c * 4);
            }
            *(unsigned long long*)(Ah + r * LDT + c * 4) = vh;
            *(unsigned long long*)(Al + r * LDT + c * 4) = vl;
        }
#pragma unroll
        for (int u = 0; u < 4; u++) {
            int idx = tid + u * 256;
            int r = idx >> 3, c = idx & 7;
            int gn = n0 + r;
            unsigned long long vh = *(const unsigned long long*)(gBh + (size_t)gn * KTOT + k0 + c * 4);
            unsigned long long vl = *(const unsigned long long*)(gBl + (size_t)gn * KTOT + k0 + c * 4);
            *(unsigned long long*)(Bh + r * LDT + c * 4) = vh;
            *(unsigned long long*)(Bl + r * LDT + c * 4) = vl;
        }
        __syncthreads();

#pragma unroll
        for (int kk = 0; kk < 2; kk++) {
            wmma::fragment<wmma::matrix_a, 16, 16, 16, __nv_bfloat16, wmma::row_major> fah[2], fal[2];
            wmma::fragment<wmma::matrix_b, 16, 16, 16, __nv_bfloat16, wmma::col_major> fbh[4], fbl[4];
#pragma unroll
            for (int i = 0; i < 2; i++) {
                wmma::load_matrix_sync(fah[i], Ah + (wm * 32 + i * 16) * LDT + kk * 16, LDT);
                wmma::load_matrix_sync(fal[i], Al + (wm * 32 + i * 16) * LDT + kk * 16, LDT);
            }
#pragma unroll
            for (int j = 0; j < 4; j++) {
                wmma::load_matrix_sync(fbh[j], Bh + (wn * 64 + j * 16) * LDT + kk * 16, LDT);
                wmma::load_matrix_sync(fbl[j], Bl + (wn * 64 + j * 16) * LDT + kk * 16, LDT);
            }
#pragma unroll
            for (int i = 0; i < 2; i++)
#pragma unroll
                for (int j = 0; j < 4; j++) {
                    wmma::mma_sync(acc[i][j], fah[i], fbh[j], acc[i][j]);
                    wmma::mma_sync(acc[i][j], fah[i], fbl[j], acc[i][j]);
                    wmma::mma_sync(acc[i][j], fal[i], fbh[j], acc[i][j]);
                }
        }
        __syncthreads();
    }

    float* stage = (float*)(sm + wid * 1280);
    const int LDS_ = 20;
#pragma unroll
    for (int i = 0; i < 2; i++)
#pragma unroll
        for (int j = 0; j < 4; j++) {
            wmma::store_matrix_sync(stage, acc[i][j], LDS_, wmma::mem_row_major);
            __syncwarp();
            int r = lane >> 1;
            int c0 = (lane & 1) * 8;
            int gm = m0 + wm * 32 + i * 16 + r;
            int gn0 = n0 + wn * 64 + j * 16 + c0;
            if (gm < Nn) {
#pragma unroll
                for (int t = 0; t < 8; t++) {
                    float v = stage[r * LDS_ + c0 + t] + bias[gn0 + t];
                    v = v > 0.0f ? v : 0.01f * v;
                    if (SRC == 0) {
                        __nv_bfloat16 h, l;
                        bsplit(v, h, l);
                        g_h1h[(size_t)gm * 256 + gn0 + t] = h;
                        g_h1l[(size_t)gm * 256 + gn0 + t] = l;
                    } else {
                        g_h2[(size_t)gm * 256 + gn0 + t] = v;
                    }
                }
            }
            __syncwarp();
        }
}

// ---------------- final linear 256->1 + softplus ----------------
__global__ void __launch_bounds__(256) k_lin3(const float* __restrict__ W3,
                                              const float* __restrict__ b3, int Nn) {
    int warp = (blockIdx.x * blockDim.x + threadIdx.x) >> 5;
    int lane = threadIdx.x & 31;
    if (warp >= Nn) return;
    const float* h = g_h2 + (size_t)warp * 256;
    float s = 0.0f;
#pragma unroll
    for (int k = 0; k < 8; k++) s = fmaf(h[lane + 32 * k], W3[lane + 32 * k], s);
#pragma unroll
    for (int o = 16; o; o >>= 1) s += __shfl_xor_sync(0xffffffffu, s, o);
    if (lane == 0) {
        float x = s + b3[0];
        g_conc[warp] = fmaxf(x, 0.0f) + log1pf(expf(-fabsf(x)));
    }
}

// ---------------- deterministic two-pass sum ----------------
__global__ void __launch_bounds__(256) k_reduce1(int Nn) {
    __shared__ float sh[256];
    float s = 0.0f;
    for (int i = blockIdx.x * 256 + threadIdx.x; i < Nn; i += 256 * 512) s += g_conc[i];
    sh[threadIdx.x] = s;
    __syncthreads();
    for (int o = 128; o; o >>= 1) {
        if (threadIdx.x < o) sh[threadIdx.x] += sh[threadIdx.x + o];
        __syncthreads();
    }
    if (threadIdx.x == 0) g_partial[blockIdx.x] = sh[0];
}
__global__ void __launch_bounds__(512) k_reduce2() {
    __shared__ float sh[512];
    sh[threadIdx.x] = g_partial[threadIdx.x];
    __syncthreads();
    for (int o = 256; o; o >>= 1) {
        if (threadIdx.x < o) sh[threadIdx.x] += sh[threadIdx.x + o];
        __syncthreads();
    }
    if (threadIdx.x == 0) g_sum = sh[0];
}
__global__ void __launch_bounds__(256) k_final(float* __restrict__ out, int Nn) {
    int i = blockIdx.x * blockDim.x + threadIdx.x;
    if (i < Nn) out[i] = g_conc[i] / (g_sum + 1e-20f);
}

// ---------------- launch ----------------
extern "C" void kernel_launch(void* const* d_in, const int* in_sizes, int n_in,
                              void* d_out, int out_size) {
    const float* state = (const float*)d_in[0];
    const int* ei = (const int*)d_in[1];
    const float* W1 = (const float*)d_in[2];
    const float* b1 = (const float*)d_in[3];
    const float* W2 = (const float*)d_in[4];
    const float* b2 = (const float*)d_in[5];
    const float* W3 = (const float*)d_in[6];
    const float* b3 = (const float*)d_in[7];
    const float* lW1 = (const float*)d_in[8];
    const float* lb1 = (const float*)d_in[9];
    const float* lW2 = (const float*)d_in[10];
    const float* lb2 = (const float*)d_in[11];
    const float* lW3 = (const float*)d_in[12];
    const float* lb3 = (const float*)d_in[13];

    int Nn = in_sizes[0] / 32;
    int E = in_sizes[1] / 2;
    const int* src = ei;
    const int* dst = ei + E;
    float* out = (float*)d_out;

    int gN = (Nn + 255) / 256;
    int gE = (E + 255) / 256;
    int gP = (Nn + 7) / 8;
    int nb = (Nn + 255) / 256;
    const int GEMM_SMEM = 40960;

    // CSR build
    k_prep<<<gN, 256>>>(Nn);
    k_cnt<<<gE, 256>>>(dst, E);
    k_scanA<<<nb, 256>>>(Nn);
    k_scanB<<<1, 512>>>(nb);
    k_scanC<<<nb, 256>>>(Nn);
    k_fill<<<gE, 256>>>(src, dst, E);
    k_convB<192, 0><<<(192 * 256 + 255) / 256, 256>>>(lW1);
    k_convB<256, 1><<<(256 * 256 + 255) / 256, 256>>>(lW2);

    // GCN stack: xw0 (writes g_xwA) then 5 fused pulls, ping-pong via template PP
    k_xw0<<<gP, 256>>>(state, W1, Nn);
    k_pull<0,   1, 0><<<gP, 256>>>(b1, W2, Nn);   // in A -> out B
    k_pull<32,  1, 1><<<gP, 256>>>(b2, W3, Nn);   // in B -> out A
    k_pull<64,  1, 0><<<gP, 256>>>(b3, W3, Nn);   // in A -> out B
    k_pull<96,  1, 1><<<gP, 256>>>(b3, W3, Nn);   // in B -> out A
    k_pull<128, 0, 0><<<gP, 256>>>(b3, W3, Nn);   // in A (no next)

    dim3 gg((Nn + 127) / 128, 2);
    k_gemm_mma<192, 0><<<gg, 256, GEMM_SMEM>>>(lb1, Nn);
    k_gemm_mma<256, 1><<<gg, 256, GEMM_SMEM>>>(lb2, Nn);

    k_lin3<<<(Nn * 32 + 255) / 256, 256>>>(lW3, lb3, Nn);
    k_reduce1<<<512, 256>>>(Nn);
    k_reduce2<<<1, 512>>>();
    k_final<<<gN, 256>>>(out, Nn);
}

// round 13
// speedup vs baseline: 1.0858x; 1.0858x over previous
#include <cuda_runtime.h>
#include <cuda_bf16.h>
#include <mma.h>
#include <cstdint>

using namespace nvcuda;

#define MAXN 100000
#define MAXE 1600000

// ---------------- static scratch (allocation-free rule) ----------------
__device__ __align__(16) int   g_cnt[MAXN];      // in-degree (excl. self loop)
__device__ __align__(16) int   g_cur[MAXN];      // fill cursors
__device__ __align__(16) int   g_rowptr[MAXN];   // CSR row starts
__device__ __align__(16) int   g_bsum[512];      // block sums for scan
__device__ __align__(16) float g_dinv[MAXN];
__device__ __align__(16) int2  g_csr[MAXE];      // (src, bitcast norm)
__device__ __align__(16) float g_xwA[MAXN * 32];
__device__ __align__(16) float g_xwB[MAXN * 32];
// bf16 hi/lo planes for MLP inputs (split-precision tensor GEMM)
__device__ __align__(16) __nv_bfloat16 g_fh[(size_t)MAXN * 192];
__device__ __align__(16) __nv_bfloat16 g_fl[(size_t)MAXN * 192];
__device__ __align__(16) __nv_bfloat16 g_h1h[(size_t)MAXN * 256];
__device__ __align__(16) __nv_bfloat16 g_h1l[(size_t)MAXN * 256];
// per-row partial dot products with W3: 4 contributors (2 warp-cols x 2 y-blocks)
__device__ __align__(16) float g_linpart[(size_t)MAXN * 4];
// weights transposed to [N][K] bf16 hi/lo
__device__ __align__(16) __nv_bfloat16 g_B1h[192 * 256];
__device__ __align__(16) __nv_bfloat16 g_B1l[192 * 256];
__device__ __align__(16) __nv_bfloat16 g_B2h[256 * 256];
__device__ __align__(16) __nv_bfloat16 g_B2l[256 * 256];
__device__ __align__(16) float g_conc[MAXN];
__device__ float g_partial[512];
__device__ float g_sum;

// bf16 hi/lo split
__device__ __forceinline__ void bsplit(float v, __nv_bfloat16& h, __nv_bfloat16& l) {
    h = __float2bfloat16(v);
    l = __float2bfloat16(v - __bfloat162float(h));
}

// ---------------- CSR build ----------------
__global__ void __launch_bounds__(256) k_prep(int Nn) {
    int i = blockIdx.x * blockDim.x + threadIdx.x;
    if (i < Nn) { g_cnt[i] = 0; g_cur[i] = 0; }
    if (i == 0) g_sum = 0.0f;
}
__global__ void __launch_bounds__(256) k_cnt(const int* __restrict__ dst, int E) {
    int e = blockIdx.x * blockDim.x + threadIdx.x;
    if (e < E) atomicAdd(&g_cnt[dst[e]], 1);
}
__global__ void __launch_bounds__(256) k_scanA(int Nn) {
    __shared__ int sh[256];
    int i = blockIdx.x * 256 + threadIdx.x;
    sh[threadIdx.x] = (i < Nn) ? g_cnt[i] : 0;
    __syncthreads();
    for (int o = 128; o; o >>= 1) {
        if (threadIdx.x < o) sh[threadIdx.x] += sh[threadIdx.x + o];
        __syncthreads();
    }
    if (threadIdx.x == 0) g_bsum[blockIdx.x] = sh[0];
}
__global__ void __launch_bounds__(512) k_scanB(int nb) {
    __shared__ int sh[512];
    int t = threadIdx.x;
    int v = (t < nb) ? g_bsum[t] : 0;
    sh[t] = v;
    __syncthreads();
    for (int o = 1; o < 512; o <<= 1) {
        int x = (t >= o) ? sh[t - o] : 0;
        __syncthreads();
        sh[t] += x;
        __syncthreads();
    }
    if (t < nb) g_bsum[t] = sh[t] - v;   // exclusive
}
__global__ void __launch_bounds__(256) k_scanC(int Nn) {
    __shared__ int sh[256];
    int i = blockIdx.x * 256 + threadIdx.x;
    int t = threadIdx.x;
    int v = (i < Nn) ? g_cnt[i] : 0;
    sh[t] = v;
    __syncthreads();
    for (int o = 1; o < 256; o <<= 1) {
        int x = (t >= o) ? sh[t - o] : 0;
        __syncthreads();
        sh[t] += x;
        __syncthreads();
    }
    if (i < Nn) {
        g_rowptr[i] = g_bsum[blockIdx.x] + sh[t] - v;
        g_dinv[i] = rsqrtf((float)(v + 1));   // + self loop
    }
}
__global__ void __launch_bounds__(256) k_fill(const int* __restrict__ src,
                                              const int* __restrict__ dst, int E) {
    int e = blockIdx.x * blockDim.x + threadIdx.x;
    if (e >= E) return;
    int s = src[e], d = dst[e];
    int pos = g_rowptr[d] + atomicAdd(&g_cur[d], 1);
    float w = g_dinv[s] * g_dinv[d];
    g_csr[pos] = make_int2(s, __float_as_int(w));
}

// ---------------- layer 1 front: xw1 = state @ W1; store state -> feat 160..191 ----
__global__ void __launch_bounds__(256) k_xw0(const float* __restrict__ state,
                                             const float* __restrict__ W, int Nn) {
    __shared__ float Ws[1024];
    int tid = threadIdx.x;
    for (int i = tid; i < 1024; i += 256) Ws[i] = W[i];
    __syncthreads();
    int lane = tid & 31;
    int node = blockIdx.x * 8 + (tid >> 5);
    if (node >= Nn) return;
    float v = state[node * 32 + lane];
    __nv_bfloat16 h, l;
    bsplit(v, h, l);
    size_t o = (size_t)node * 192 + 160 + lane;
    g_fh[o] = h;
    g_fl[o] = l;
    float acc = 0.0f;
#pragma unroll
    for (int k = 0; k < 32; k++) {
        float xk = __shfl_sync(0xffffffffu, v, k);
        acc = fmaf(xk, Ws[k * 32 + lane], acc);
    }
    g_xwA[node * 32 + lane] = acc;
}

// ---------------- fused pull layer (R10 form — plain loop) ----------
template <int FCOL, int HASNEXT, int PP>
__global__ void __launch_bounds__(256) k_pull(const float* __restrict__ b_cur,
                                              const float* __restrict__ Wnext, int Nn) {
    const float* __restrict__ xw_in = PP ? g_xwB : g_xwA;
    float* __restrict__ xw_out      = PP ? g_xwA : g_xwB;
    __shared__ float Ws[1024];
    int tid = threadIdx.x;
    if (HASNEXT) {
        for (int i = tid; i < 1024; i += 256) Ws[i] = Wnext[i];
        __syncthreads();
    }
    int lane = tid & 31;
    int node = blockIdx.x * 8 + (tid >> 5);
    if (node >= Nn) return;

    float di = g_dinv[node];
    float acc = di * di * xw_in[node * 32 + lane] + b_cur[lane];
    int start = g_rowptr[node];
    int cnt = g_cnt[node];
    for (int e = 0; e < cnt; e++) {
        int2 p = g_csr[start + e];
        acc = fmaf(__int_as_float(p.y), xw_in[(size_t)p.x * 32 + lane], acc);
    }
    float v = fmaxf(acc, 0.0f);
    __nv_bfloat16 h, l;
    bsplit(v, h, l);
    size_t o = (size_t)node * 192 + FCOL + lane;
    g_fh[o] = h;
    g_fl[o] = l;
    if (HASNEXT) {
        float a2 = 0.0f;
#pragma unroll
        for (int k = 0; k < 32; k++) {
            float xk = __shfl_sync(0xffffffffu, v, k);
            a2 = fmaf(xk, Ws[k * 32 + lane], a2);
        }
        xw_out[node * 32 + lane] = a2;
    }
}

// ---------------- weight convert + transpose: W[K][256] -> [N][K] bf16 hi/lo ----
template <int K, int WHICH>
__global__ void __launch_bounds__(256) k_convB(const float* __restrict__ Wt) {
    int idx = blockIdx.x * blockDim.x + threadIdx.x;
    if (idx >= K * 256) return;
    int k = idx >> 8, n = idx & 255;
    __nv_bfloat16 h, l;
    bsplit(Wt[idx], h, l);
    if (WHICH == 0) { g_B1h[n * K + k] = h; g_B1l[n * K + k] = l; }
    else           { g_B2h[n * K + k] = h; g_B2l[n * K + k] = l; }
}

// ---------------- wmma bf16x3 split GEMM ----------------
// SRC 0: A=feat (K=192) -> h1 bf16 hi/lo (leaky applied)
// SRC 1: A=h1 (K=256) -> fused final linear: partial dot with W3 per row,
//        written to g_linpart[row*4 + (wn + 2*blockIdx.y)]  (no h2 buffer)
template <int KTOT, int SRC>
__global__ void __launch_bounds__(256) k_gemm_mma(const float* __restrict__ bias,
                                                  const float* __restrict__ W3, int Nn) {
    extern __shared__ char sm[];
    const int LDT = 40;
    __nv_bfloat16* Ah = (__nv_bfloat16*)(sm);
    __nv_bfloat16* Al = (__nv_bfloat16*)(sm + 10240);
    __nv_bfloat16* Bh = (__nv_bfloat16*)(sm + 20480);
    __nv_bfloat16* Bl = (__nv_bfloat16*)(sm + 30720);

    int tid = threadIdx.x;
    int wid = tid >> 5, lane = tid & 31;
    int wm = wid & 3, wn = wid >> 2;
    int m0 = blockIdx.x * 128;
    int n0 = blockIdx.y * 128;

    const __nv_bfloat16* gAh = (SRC == 0) ? g_fh : g_h1h;
    const __nv_bfloat16* gAl = (SRC == 0) ? g_fl : g_h1l;
    const __nv_bfloat16* gBh = (SRC == 0) ? g_B1h : g_B2h;
    const __nv_bfloat16* gBl = (SRC == 0) ? g_B1l : g_B2l;

    wmma::fragment<wmma::accumulator, 16, 16, 16, float> acc[2][4];
#pragma unroll
    for (int i = 0; i < 2; i++)
#pragma unroll
        for (int j = 0; j < 4; j++) wmma::fill_fragment(acc[i][j], 0.0f);

    for (int k0 = 0; k0 < KTOT; k0 += 32) {
#pragma unroll
        for (int u = 0; u < 4; u++) {
            int idx = tid + u * 256;
            int r = idx >> 3, c = idx & 7;
            int gm = m0 + r;
            unsigned long long vh = 0ull, vl = 0ull;
            if (gm < Nn) {
                vh = *(const unsigned long long*)(gAh + (size_t)gm * KTOT + k0 + c * 4);
                vl = *(const unsigned long long*)(gAl + (size_t)gm * KTOT + k0 + c * 4);
            }
            *(unsigned long long*)(Ah + r * LDT + c * 4) = vh;
            *(unsigned long long*)(Al + r * LDT + c * 4) = vl;
        }
#pragma unroll
        for (int u = 0; u < 4; u++) {
            int idx = tid + u * 256;
            int r = idx >> 3, c = idx & 7;
            int gn = n0 + r;
            unsigned long long vh = *(const unsigned long long*)(gBh + (size_t)gn * KTOT + k0 + c * 4);
            unsigned long long vl = *(const unsigned long long*)(gBl + (size_t)gn * KTOT + k0 + c * 4);
            *(unsigned long long*)(Bh + r * LDT + c * 4) = vh;
            *(unsigned long long*)(Bl + r * LDT + c * 4) = vl;
        }
        __syncthreads();

#pragma unroll
        for (int kk = 0; kk < 2; kk++) {
            wmma::fragment<wmma::matrix_a, 16, 16, 16, __nv_bfloat16, wmma::row_major> fah[2], fal[2];
            wmma::fragment<wmma::matrix_b, 16, 16, 16, __nv_bfloat16, wmma::col_major> fbh[4], fbl[4];
#pragma unroll
            for (int i = 0; i < 2; i++) {
                wmma::load_matrix_sync(fah[i], Ah + (wm * 32 + i * 16) * LDT + kk * 16, LDT);
                wmma::load_matrix_sync(fal[i], Al + (wm * 32 + i * 16) * LDT + kk * 16, LDT);
            }
#pragma unroll
            for (int j = 0; j < 4; j++) {
                wmma::load_matrix_sync(fbh[j], Bh + (wn * 64 + j * 16) * LDT + kk * 16, LDT);
                wmma::load_matrix_sync(fbl[j], Bl + (wn * 64 + j * 16) * LDT + kk * 16, LDT);
            }
#pragma unroll
            for (int i = 0; i < 2; i++)
#pragma unroll
                for (int j = 0; j < 4; j++) {
                    wmma::mma_sync(acc[i][j], fah[i], fbh[j], acc[i][j]);
                    wmma::mma_sync(acc[i][j], fah[i], fbl[j], acc[i][j]);
                    wmma::mma_sync(acc[i][j], fal[i], fbh[j], acc[i][j]);
                }
        }
        __syncthreads();
    }

    float* stage = (float*)(sm + wid * 1280);
    const int LDS_ = 20;
    float dot[2] = {0.0f, 0.0f};   // per-thread partial dot with W3 (SRC==1)
#pragma unroll
    for (int i = 0; i < 2; i++)
#pragma unroll
        for (int j = 0; j < 4; j++) {
            wmma::store_matrix_sync(stage, acc[i][j], LDS_, wmma::mem_row_major);
            __syncwarp();
            int r = lane >> 1;
            int c0 = (lane & 1) * 8;
            int gm = m0 + wm * 32 + i * 16 + r;
            int gn0 = n0 + wn * 64 + j * 16 + c0;
            if (gm < Nn) {
#pragma unroll
                for (int t = 0; t < 8; t++) {
                    float v = stage[r * LDS_ + c0 + t] + bias[gn0 + t];
                    v = v > 0.0f ? v : 0.01f * v;   // leaky_relu 0.01
                    if (SRC == 0) {
                        __nv_bfloat16 h, l;
                        bsplit(v, h, l);
                        g_h1h[(size_t)gm * 256 + gn0 + t] = h;
                        g_h1l[(size_t)gm * 256 + gn0 + t] = l;
                    } else {
                        dot[i] = fmaf(v, W3[gn0 + t], dot[i]);
                    }
                }
            }
            __syncwarp();
        }
    if (SRC == 1) {
        int cid = wn + 2 * blockIdx.y;   // contributor slot 0..3
#pragma unroll
        for (int i = 0; i < 2; i++) {
            float s = dot[i] + __shfl_xor_sync(0xffffffffu, dot[i], 1);
            int gm = m0 + wm * 32 + i * 16 + (lane >> 1);
            if ((lane & 1) == 0 && gm < Nn) g_linpart[(size_t)gm * 4 + cid] = s;
        }
    }
}

// ---------------- softplus over summed partials ----------------
__global__ void __launch_bounds__(256) k_softp(const float* __restrict__ b3, int Nn) {
    int i = blockIdx.x * blockDim.x + threadIdx.x;
    if (i >= Nn) return;
    const float4 p = *(const float4*)(g_linpart + (size_t)i * 4);
    float x = ((p.x + p.y) + (p.z + p.w)) + b3[0];   // fixed order: deterministic
    g_conc[i] = fmaxf(x, 0.0f) + log1pf(expf(-fabsf(x)));
}

// ---------------- deterministic two-pass sum ----------------
__global__ void __launch_bounds__(256) k_reduce1(int Nn) {
    __shared__ float sh[256];
    float s = 0.0f;
    for (int i = blockIdx.x * 256 + threadIdx.x; i < Nn; i += 256 * 512) s += g_conc[i];
    sh[threadIdx.x] = s;
    __syncthreads();
    for (int o = 128; o; o >>= 1) {
        if (threadIdx.x < o) sh[threadIdx.x] += sh[threadIdx.x + o];
        __syncthreads();
    }
    if (threadIdx.x == 0) g_partial[blockIdx.x] = sh[0];
}
__global__ void __launch_bounds__(512) k_reduce2() {
    __shared__ float sh[512];
    sh[threadIdx.x] = g_partial[threadIdx.x];
    __syncthreads();
    for (int o = 256; o; o >>= 1) {
        if (threadIdx.x < o) sh[threadIdx.x] += sh[threadIdx.x + o];
        __syncthreads();
    }
    if (threadIdx.x == 0) g_sum = sh[0];
}
__global__ void __launch_bounds__(256) k_final(float* __restrict__ out, int Nn) {
    int i = blockIdx.x * blockDim.x + threadIdx.x;
    if (i < Nn) out[i] = g_conc[i] / (g_sum + 1e-20f);
}

// ---------------- launch ----------------
extern "C" void kernel_launch(void* const* d_in, const int* in_sizes, int n_in,
                              void* d_out, int out_size) {
    const float* state = (const float*)d_in[0];
    const int* ei = (const int*)d_in[1];
    const float* W1 = (const float*)d_in[2];
    const float* b1 = (const float*)d_in[3];
    const float* W2 = (const float*)d_in[4];
    const float* b2 = (const float*)d_in[5];
    const float* W3 = (const float*)d_in[6];
    const float* b3 = (const float*)d_in[7];
    const float* lW1 = (const float*)d_in[8];
    const float* lb1 = (const float*)d_in[9];
    const float* lW2 = (const float*)d_in[10];
    const float* lb2 = (const float*)d_in[11];
    const float* lW3 = (const float*)d_in[12];
    const float* lb3 = (const float*)d_in[13];

    int Nn = in_sizes[0] / 32;
    int E = in_sizes[1] / 2;
    const int* src = ei;
    const int* dst = ei + E;
    float* out = (float*)d_out;

    int gN = (Nn + 255) / 256;
    int gE = (E + 255) / 256;
    int gP = (Nn + 7) / 8;
    int nb = (Nn + 255) / 256;
    const int GEMM_SMEM = 40960;

    // CSR build
    k_prep<<<gN, 256>>>(Nn);
    k_cnt<<<gE, 256>>>(dst, E);
    k_scanA<<<nb, 256>>>(Nn);
    k_scanB<<<1, 512>>>(nb);
    k_scanC<<<nb, 256>>>(Nn);
    k_fill<<<gE, 256>>>(src, dst, E);
    k_convB<192, 0><<<(192 * 256 + 255) / 256, 256>>>(lW1);
    k_convB<256, 1><<<(256 * 256 + 255) / 256, 256>>>(lW2);

    // GCN stack: xw0 (writes g_xwA) then 5 fused pulls, ping-pong via template PP
    k_xw0<<<gP, 256>>>(state, W1, Nn);
    k_pull<0,   1, 0><<<gP, 256>>>(b1, W2, Nn);   // in A -> out B
    k_pull<32,  1, 1><<<gP, 256>>>(b2, W3, Nn);   // in B -> out A
    k_pull<64,  1, 0><<<gP, 256>>>(b3, W3, Nn);   // in A -> out B
    k_pull<96,  1, 1><<<gP, 256>>>(b3, W3, Nn);   // in B -> out A
    k_pull<128, 0, 0><<<gP, 256>>>(b3, W3, Nn);   // in A (no next)

    dim3 gg((Nn + 127) / 128, 2);
    k_gemm_mma<192, 0><<<gg, 256, GEMM_SMEM>>>(lb1, lW3, Nn);
    k_gemm_mma<256, 1><<<gg, 256, GEMM_SMEM>>>(lb2, lW3, Nn);

    k_softp<<<gN, 256>>>(lb3, Nn);
    k_reduce1<<<512, 256>>>(Nn);
    k_reduce2<<<1, 512>>>();
    k_final<<<gN, 256>>>(out, Nn);
}

// round 15
// speedup vs baseline: 1.1968x; 1.1022x over previous
#include <cuda_runtime.h>
#include <cuda_bf16.h>
#include <mma.h>
#include <cstdint>

using namespace nvcuda;

#define MAXN 100000
#define MAXE 1600000

// ---------------- static scratch (allocation-free rule) ----------------
__device__ __align__(16) int   g_cnt[MAXN];
__device__ __align__(16) int   g_cur[MAXN];
__device__ __align__(16) int   g_rowptr[MAXN];
__device__ __align__(16) int   g_bsum[512];
__device__ __align__(16) float g_dinv[MAXN];
__device__ __align__(16) int2  g_csr[MAXE];
__device__ __align__(16) float g_xwA[MAXN * 32];
__device__ __align__(16) float g_xwB[MAXN * 32];
__device__ __align__(16) __nv_bfloat16 g_fh[(size_t)MAXN * 192];
__device__ __align__(16) __nv_bfloat16 g_fl[(size_t)MAXN * 192];
__device__ __align__(16) __nv_bfloat16 g_h1h[(size_t)MAXN * 256];
__device__ __align__(16) __nv_bfloat16 g_h1l[(size_t)MAXN * 256];
__device__ __align__(16) float g_linpart[(size_t)MAXN * 4];
__device__ __align__(16) __nv_bfloat16 g_B1h[192 * 256];
__device__ __align__(16) __nv_bfloat16 g_B1l[192 * 256];
__device__ __align__(16) __nv_bfloat16 g_B2h[256 * 256];
__device__ __align__(16) __nv_bfloat16 g_B2l[256 * 256];
__device__ __align__(16) float g_conc[MAXN];
__device__ float g_partial[512];
__device__ float g_sum;

__device__ __forceinline__ void bsplit(float v, __nv_bfloat16& h, __nv_bfloat16& l) {
    h = __float2bfloat16(v);
    l = __float2bfloat16(v - __bfloat162float(h));
}
__device__ __forceinline__ void cpasync16(void* dst_smem, const void* src) {
    uint32_t d = (uint32_t)__cvta_generic_to_shared(dst_smem);
    asm volatile("cp.async.cg.shared.global [%0], [%1], 16;" :: "r"(d), "l"(src));
}
#define CP_COMMIT() asm volatile("cp.async.commit_group;" ::: "memory")

// ---------------- CSR build ----------------
__global__ void __launch_bounds__(256) k_prep(int Nn) {
    int i = blockIdx.x * blockDim.x + threadIdx.x;
    if (i < Nn) { g_cnt[i] = 0; g_cur[i] = 0; }
    if (i == 0) g_sum = 0.0f;
}
__global__ void __launch_bounds__(256) k_cnt(const int* __restrict__ dst, int E) {
    int e = blockIdx.x * blockDim.x + threadIdx.x;
    if (e < E) atomicAdd(&g_cnt[dst[e]], 1);
}
__global__ void __launch_bounds__(256) k_scanA(int Nn) {
    __shared__ int sh[256];
    int i = blockIdx.x * 256 + threadIdx.x;
    sh[threadIdx.x] = (i < Nn) ? g_cnt[i] : 0;
    __syncthreads();
    for (int o = 128; o; o >>= 1) {
        if (threadIdx.x < o) sh[threadIdx.x] += sh[threadIdx.x + o];
        __syncthreads();
    }
    if (threadIdx.x == 0) g_bsum[blockIdx.x] = sh[0];
}
__global__ void __launch_bounds__(512) k_scanB(int nb) {
    __shared__ int sh[512];
    int t = threadIdx.x;
    int v = (t < nb) ? g_bsum[t] : 0;
    sh[t] = v;
    __syncthreads();
    for (int o = 1; o < 512; o <<= 1) {
        int x = (t >= o) ? sh[t - o] : 0;
        __syncthreads();
        sh[t] += x;
        __syncthreads();
    }
    if (t < nb) g_bsum[t] = sh[t] - v;
}
__global__ void __launch_bounds__(256) k_scanC(int Nn) {
    __shared__ int sh[256];
    int i = blockIdx.x * 256 + threadIdx.x;
    int t = threadIdx.x;
    int v = (i < Nn) ? g_cnt[i] : 0;
    sh[t] = v;
    __syncthreads();
    for (int o = 1; o < 256; o <<= 1) {
        int x = (t >= o) ? sh[t - o] : 0;
        __syncthreads();
        sh[t] += x;
        __syncthreads();
    }
    if (i < Nn) {
        g_rowptr[i] = g_bsum[blockIdx.x] + sh[t] - v;
        g_dinv[i] = rsqrtf((float)(v + 1));
    }
}
__global__ void __launch_bounds__(256) k_fill(const int* __restrict__ src,
                                              const int* __restrict__ dst, int E) {
    int e = blockIdx.x * blockDim.x + threadIdx.x;
    if (e >= E) return;
    int s = src[e], d = dst[e];
    int pos = g_rowptr[d] + atomicAdd(&g_cur[d], 1);
    float w = g_dinv[s] * g_dinv[d];
    g_csr[pos] = make_int2(s, __float_as_int(w));
}

// ---------------- layer 1 front ----------------
__global__ void __launch_bounds__(256) k_xw0(const float* __restrict__ state,
                                             const float* __restrict__ W, int Nn) {
    __shared__ float Ws[1024];
    int tid = threadIdx.x;
    for (int i = tid; i < 1024; i += 256) Ws[i] = W[i];
    __syncthreads();
    int lane = tid & 31;
    int node = blockIdx.x * 8 + (tid >> 5);
    if (node >= Nn) return;
    float v = state[node * 32 + lane];
    __nv_bfloat16 h, l;
    bsplit(v, h, l);
    size_t o = (size_t)node * 192 + 160 + lane;
    g_fh[o] = h;
    g_fl[o] = l;
    float acc = 0.0f;
#pragma unroll
    for (int k = 0; k < 32; k++) {
        float xk = __shfl_sync(0xffffffffu, v, k);
        acc = fmaf(xk, Ws[k * 32 + lane], acc);
    }
    g_xwA[node * 32 + lane] = acc;
}

// ---------------- fused pull layer (R10 form) ----------
template <int FCOL, int HASNEXT, int PP>
__global__ void __launch_bounds__(256) k_pull(const float* __restrict__ b_cur,
                                              const float* __restrict__ Wnext, int Nn) {
    const float* __restrict__ xw_in = PP ? g_xwB : g_xwA;
    float* __restrict__ xw_out      = PP ? g_xwA : g_xwB;
    __shared__ float Ws[1024];
    int tid = threadIdx.x;
    if (HASNEXT) {
        for (int i = tid; i < 1024; i += 256) Ws[i] = Wnext[i];
        __syncthreads();
    }
    int lane = tid & 31;
    int node = blockIdx.x * 8 + (tid >> 5);
    if (node >= Nn) return;

    float di = g_dinv[node];
    float acc = di * di * xw_in[node * 32 + lane] + b_cur[lane];
    int start = g_rowptr[node];
    int cnt = g_cnt[node];
    for (int e = 0; e < cnt; e++) {
        int2 p = g_csr[start + e];
        acc = fmaf(__int_as_float(p.y), xw_in[(size_t)p.x * 32 + lane], acc);
    }
    float v = fmaxf(acc, 0.0f);
    __nv_bfloat16 h, l;
    bsplit(v, h, l);
    size_t o = (size_t)node * 192 + FCOL + lane;
    g_fh[o] = h;
    g_fl[o] = l;
    if (HASNEXT) {
        float a2 = 0.0f;
#pragma unroll
        for (int k = 0; k < 32; k++) {
            float xk = __shfl_sync(0xffffffffu, v, k);
            a2 = fmaf(xk, Ws[k * 32 + lane], a2);
        }
        xw_out[node * 32 + lane] = a2;
    }
}

// ---------------- weight convert ----------------
template <int K, int WHICH>
__global__ void __launch_bounds__(256) k_convB(const float* __restrict__ Wt) {
    int idx = blockIdx.x * blockDim.x + threadIdx.x;
    if (idx >= K * 256) return;
    int k = idx >> 8, n = idx & 255;
    __nv_bfloat16 h, l;
    bsplit(Wt[idx], h, l);
    if (WHICH == 0) { g_B1h[n * K + k] = h; g_B1l[n * K + k] = l; }
    else           { g_B2h[n * K + k] = h; g_B2l[n * K + k] = l; }
}

// ---------------- wmma bf16x3 split GEMM, cp.async 2-stage pipeline ----------------
template <int KTOT, int SRC>
__global__ void __launch_bounds__(256) k_gemm_mma(const float* __restrict__ bias,
                                                  const float* __restrict__ W3, int Nn) {
    extern __shared__ char sm[];
    const int LDT = 40;
    const int STG = 40960;

    int tid = threadIdx.x;
    int wid = tid >> 5, lane = tid & 31;
    int wm = wid & 3, wn = wid >> 2;
    int m0 = blockIdx.x * 128;
    int n0 = blockIdx.y * 128;

    const __nv_bfloat16* gAh = (SRC == 0) ? g_fh : g_h1h;
    const __nv_bfloat16* gAl = (SRC == 0) ? g_fl : g_h1l;
    const __nv_bfloat16* gBh = (SRC == 0) ? g_B1h : g_B2h;
    const __nv_bfloat16* gBl = (SRC == 0) ? g_B1l : g_B2l;

    const int NCH = KTOT / 32;

    auto issue = [&](int ch, int stg) {
        int k0 = ch * 32;
        char* base = sm + stg * STG;
#pragma unroll
        for (int u = 0; u < 2; u++) {
            int idx = tid + u * 256;        // 0..511
            int r = idx >> 2, c = idx & 3;  // row, 16B chunk (8 bf16)
            int gm = m0 + r; if (gm >= Nn) gm = Nn - 1;
            int gn = n0 + r;
            size_t ao = (size_t)gm * KTOT + k0 + c * 8;
            size_t bo = (size_t)gn * KTOT + k0 + c * 8;
            int so = r * (LDT * 2) + c * 16;
            cpasync16(base + so,          gAh + ao);
            cpasync16(base + 10240 + so,  gAl + ao);
            cpasync16(base + 20480 + so,  gBh + bo);
            cpasync16(base + 30720 + so,  gBl + bo);
        }
    };

    wmma::fragment<wmma::accumulator, 16, 16, 16, float> acc[2][4];
#pragma unroll
    for (int i = 0; i < 2; i++)
#pragma unroll
        for (int j = 0; j < 4; j++) wmma::fill_fragment(acc[i][j], 0.0f);

    issue(0, 0);
    CP_COMMIT();

    for (int ch = 0; ch < NCH; ch++) {
        if (ch + 1 < NCH) {
            issue(ch + 1, (ch + 1) & 1);
            CP_COMMIT();
            asm volatile("cp.async.wait_group 1;" ::: "memory");
        } else {
            asm volatile("cp.async.wait_group 0;" ::: "memory");
        }
        __syncthreads();

        char* base = sm + (ch & 1) * STG;
        __nv_bfloat16* Ah = (__nv_bfloat16*)(base);
        __nv_bfloat16* Al = (__nv_bfloat16*)(base + 10240);
        __nv_bfloat16* Bh = (__nv_bfloat16*)(base + 20480);
        __nv_bfloat16* Bl = (__nv_bfloat16*)(base + 30720);

#pragma unroll
        for (int kk = 0; kk < 2; kk++) {
            wmma::fragment<wmma::matrix_a, 16, 16, 16, __nv_bfloat16, wmma::row_major> fah[2], fal[2];
            wmma::fragment<wmma::matrix_b, 16, 16, 16, __nv_bfloat16, wmma::col_major> fbh[4], fbl[4];
#pragma unroll
            for (int i = 0; i < 2; i++) {
                wmma::load_matrix_sync(fah[i], Ah + (wm * 32 + i * 16) * LDT + kk * 16, LDT);
                wmma::load_matrix_sync(fal[i], Al + (wm * 32 + i * 16) * LDT + kk * 16, LDT);
            }
#pragma unroll
            for (int j = 0; j < 4; j++) {
                wmma::load_matrix_sync(fbh[j], Bh + (wn * 64 + j * 16) * LDT + kk * 16, LDT);
                wmma::load_matrix_sync(fbl[j], Bl + (wn * 64 + j * 16) * LDT + kk * 16, LDT);
            }
#pragma unroll
            for (int i = 0; i < 2; i++)
#pragma unroll
                for (int j = 0; j < 4; j++) {
                    wmma::mma_sync(acc[i][j], fah[i], fbh[j], acc[i][j]);
                    wmma::mma_sync(acc[i][j], fah[i], fbl[j], acc[i][j]);
                    wmma::mma_sync(acc[i][j], fal[i], fbh[j], acc[i][j]);
                }
        }
        __syncthreads();   // before next issue() overwrites this stage
    }

    // epilogue (stage buffers free now)
    float* stage = (float*)(sm + wid * 1280);
    const int LDS_ = 20;
    float dot[2] = {0.0f, 0.0f};
#pragma unroll
    for (int i = 0; i < 2; i++)
#pragma unroll
        for (int j = 0; j < 4; j++) {
            wmma::store_matrix_sync(stage, acc[i][j], LDS_, wmma::mem_row_major);
            __syncwarp();
            int r = lane >> 1;
            int c0 = (lane & 1) * 8;
            int gm = m0 + wm * 32 + i * 16 + r;
            int gn0 = n0 + wn * 64 + j * 16 + c0;
            if (gm < Nn) {
#pragma unroll
                for (int t = 0; t < 8; t++) {
                    float v = stage[r * LDS_ + c0 + t] + bias[gn0 + t];
                    v = v > 0.0f ? v : 0.01f * v;
                    if (SRC == 0) {
                        __nv_bfloat16 h, l;
                        bsplit(v, h, l);
                        g_h1h[(size_t)gm * 256 + gn0 + t] = h;
                        g_h1l[(size_t)gm * 256 + gn0 + t] = l;
                    } else {
                        dot[i] = fmaf(v, W3[gn0 + t], dot[i]);
                    }
                }
            }
            __syncwarp();
        }
    if (SRC == 1) {
        int cid = wn + 2 * blockIdx.y;
#pragma unroll
        for (int i = 0; i < 2; i++) {
            float s = dot[i] + __shfl_xor_sync(0xffffffffu, dot[i], 1);
            int gm = m0 + wm * 32 + i * 16 + (lane >> 1);
            if ((lane & 1) == 0 && gm < Nn) g_linpart[(size_t)gm * 4 + cid] = s;
        }
    }
}

// ---------------- softplus over summed partials ----------------
__global__ void __launch_bounds__(256) k_softp(const float* __restrict__ b3, int Nn) {
    int i = blockIdx.x * blockDim.x + threadIdx.x;
    if (i >= Nn) return;
    const float4 p = *(const float4*)(g_linpart + (size_t)i * 4);
    float x = ((p.x + p.y) + (p.z + p.w)) + b3[0];
    g_conc[i] = fmaxf(x, 0.0f) + log1pf(expf(-fabsf(x)));
}

// ---------------- deterministic two-pass sum ----------------
__global__ void __launch_bounds__(256) k_reduce1(int Nn) {
    __shared__ float sh[256];
    float s = 0.0f;
    for (int i = blockIdx.x * 256 + threadIdx.x; i < Nn; i += 256 * 512) s += g_conc[i];
    sh[threadIdx.x] = s;
    __syncthreads();
    for (int o = 128; o; o >>= 1) {
        if (threadIdx.x < o) sh[threadIdx.x] += sh[threadIdx.x + o];
        __syncthreads();
    }
    if (threadIdx.x == 0) g_partial[blockIdx.x] = sh[0];
}
__global__ void __launch_bounds__(512) k_reduce2() {
    __shared__ float sh[512];
    sh[threadIdx.x] = g_partial[threadIdx.x];
    __syncthreads();
    for (int o = 256; o; o >>= 1) {
        if (threadIdx.x < o) sh[threadIdx.x] += sh[threadIdx.x + o];
        __syncthreads();
    }
    if (threadIdx.x == 0) g_sum = sh[0];
}
__global__ void __launch_bounds__(256) k_final(float* __restrict__ out, int Nn) {
    int i = blockIdx.x * blockDim.x + threadIdx.x;
    if (i < Nn) out[i] = g_conc[i] / (g_sum + 1e-20f);
}

// ---------------- launch ----------------
extern "C" void kernel_launch(void* const* d_in, const int* in_sizes, int n_in,
                              void* d_out, int out_size) {
    const float* state = (const float*)d_in[0];
    const int* ei = (const int*)d_in[1];
    const float* W1 = (const float*)d_in[2];
    const float* b1 = (const float*)d_in[3];
    const float* W2 = (const float*)d_in[4];
    const float* b2 = (const float*)d_in[5];
    const float* W3 = (const float*)d_in[6];
    const float* b3 = (const float*)d_in[7];
    const float* lW1 = (const float*)d_in[8];
    const float* lb1 = (const float*)d_in[9];
    const float* lW2 = (const float*)d_in[10];
    const float* lb2 = (const float*)d_in[11];
    const float* lW3 = (const float*)d_in[12];
    const float* lb3 = (const float*)d_in[13];

    int Nn = in_sizes[0] / 32;
    int E = in_sizes[1] / 2;
    const int* src = ei;
    const int* dst = ei + E;
    float* out = (float*)d_out;

    int gN = (Nn + 255) / 256;
    int gE = (E + 255) / 256;
    int gP = (Nn + 7) / 8;
    int nb = (Nn + 255) / 256;
    const int GEMM_SMEM = 81920;

    // idempotent, called every invocation (no static guards per harness rules)
    cudaFuncSetAttribute((const void*)k_gemm_mma<192, 0>,
                         cudaFuncAttributeMaxDynamicSharedMemorySize, GEMM_SMEM);
    cudaFuncSetAttribute((const void*)k_gemm_mma<256, 1>,
                         cudaFuncAttributeMaxDynamicSharedMemorySize, GEMM_SMEM);

    // CSR build
    k_prep<<<gN, 256>>>(Nn);
    k_cnt<<<gE, 256>>>(dst, E);
    k_scanA<<<nb, 256>>>(Nn);
    k_scanB<<<1, 512>>>(nb);
    k_scanC<<<nb, 256>>>(Nn);
    k_fill<<<gE, 256>>>(src, dst, E);
    k_convB<192, 0><<<(192 * 256 + 255) / 256, 256>>>(lW1);
    k_convB<256, 1><<<(256 * 256 + 255) / 256, 256>>>(lW2);

    // GCN stack
    k_xw0<<<gP, 256>>>(state, W1, Nn);
    k_pull<0,   1, 0><<<gP, 256>>>(b1, W2, Nn);
    k_pull<32,  1, 1><<<gP, 256>>>(b2, W3, Nn);
    k_pull<64,  1, 0><<<gP, 256>>>(b3, W3, Nn);
    k_pull<96,  1, 1><<<gP, 256>>>(b3, W3, Nn);
    k_pull<128, 0, 0><<<gP, 256>>>(b3, W3, Nn);

    dim3 gg((Nn + 127) / 128, 2);
    k_gemm_mma<192, 0><<<gg, 256, GEMM_SMEM>>>(lb1, lW3, Nn);
    k_gemm_mma<256, 1><<<gg, 256, GEMM_SMEM>>>(lb2, lW3, Nn);

    k_softp<<<gN, 256>>>(lb3, Nn);
    k_reduce1<<<512, 256>>>(Nn);
    k_reduce2<<<1, 512>>>();
    k_final<<<gN, 256>>>(out, Nn);
}

// round 16
// speedup vs baseline: 1.2487x; 1.0434x over previous
#include <cuda_runtime.h>
#include <cuda_bf16.h>
#include <mma.h>
#include <cstdint>

using namespace nvcuda;

#define MAXN 100000
#define MAXE 1600000

// ---------------- static scratch (allocation-free rule) ----------------
__device__ __align__(16) int   g_cnt[MAXN];
__device__ __align__(16) int   g_cur[MAXN];
__device__ __align__(16) int   g_rowptr[MAXN];
__device__ __align__(16) int   g_bsum[512];
__device__ __align__(16) float g_dinv[MAXN];
__device__ __align__(16) int   g_csri[MAXE];     // src only (dinv pre-scaled xw)
__device__ __align__(16) float g_xwA[MAXN * 32];
__device__ __align__(16) float g_xwB[MAXN * 32];
__device__ __align__(16) __nv_bfloat16 g_fh[(size_t)MAXN * 192];
__device__ __align__(16) __nv_bfloat16 g_fl[(size_t)MAXN * 192];
__device__ __align__(16) __nv_bfloat16 g_h1h[(size_t)MAXN * 256];
__device__ __align__(16) __nv_bfloat16 g_h1l[(size_t)MAXN * 256];
__device__ __align__(16) float g_linpart[(size_t)MAXN * 4];
__device__ __align__(16) __nv_bfloat16 g_B1h[192 * 256];
__device__ __align__(16) __nv_bfloat16 g_B1l[192 * 256];
__device__ __align__(16) __nv_bfloat16 g_B2h[256 * 256];
__device__ __align__(16) __nv_bfloat16 g_B2l[256 * 256];
__device__ __align__(16) float g_conc[MAXN];
__device__ float g_partial[512];
__device__ float g_sum;

__device__ __forceinline__ void bsplit(float v, __nv_bfloat16& h, __nv_bfloat16& l) {
    h = __float2bfloat16(v);
    l = __float2bfloat16(v - __bfloat162float(h));
}
__device__ __forceinline__ void cpasync16(void* dst_smem, const void* src) {
    uint32_t d = (uint32_t)__cvta_generic_to_shared(dst_smem);
    asm volatile("cp.async.cg.shared.global [%0], [%1], 16;" :: "r"(d), "l"(src));
}
#define CP_COMMIT() asm volatile("cp.async.commit_group;" ::: "memory")

// ---------------- CSR build ----------------
__global__ void __launch_bounds__(256) k_prep(int Nn) {
    int i = blockIdx.x * blockDim.x + threadIdx.x;
    if (i < Nn) { g_cnt[i] = 0; g_cur[i] = 0; }
    if (i == 0) g_sum = 0.0f;
}
__global__ void __launch_bounds__(256) k_cnt(const int* __restrict__ dst, int E) {
    int e = blockIdx.x * blockDim.x + threadIdx.x;
    if (e < E) atomicAdd(&g_cnt[dst[e]], 1);
}
__global__ void __launch_bounds__(256) k_scanA(int Nn) {
    __shared__ int sh[256];
    int i = blockIdx.x * 256 + threadIdx.x;
    sh[threadIdx.x] = (i < Nn) ? g_cnt[i] : 0;
    __syncthreads();
    for (int o = 128; o; o >>= 1) {
        if (threadIdx.x < o) sh[threadIdx.x] += sh[threadIdx.x + o];
        __syncthreads();
    }
    if (threadIdx.x == 0) g_bsum[blockIdx.x] = sh[0];
}
__global__ void __launch_bounds__(512) k_scanB(int nb) {
    __shared__ int sh[512];
    int t = threadIdx.x;
    int v = (t < nb) ? g_bsum[t] : 0;
    sh[t] = v;
    __syncthreads();
    for (int o = 1; o < 512; o <<= 1) {
        int x = (t >= o) ? sh[t - o] : 0;
        __syncthreads();
        sh[t] += x;
        __syncthreads();
    }
    if (t < nb) g_bsum[t] = sh[t] - v;
}
__global__ void __launch_bounds__(256) k_scanC(int Nn) {
    __shared__ int sh[256];
    int i = blockIdx.x * 256 + threadIdx.x;
    int t = threadIdx.x;
    int v = (i < Nn) ? g_cnt[i] : 0;
    sh[t] = v;
    __syncthreads();
    for (int o = 1; o < 256; o <<= 1) {
        int x = (t >= o) ? sh[t - o] : 0;
        __syncthreads();
        sh[t] += x;
        __syncthreads();
    }
    if (i < Nn) {
        g_rowptr[i] = g_bsum[blockIdx.x] + sh[t] - v;
        g_dinv[i] = rsqrtf((float)(v + 1));
    }
}
__global__ void __launch_bounds__(256) k_fill(const int* __restrict__ src,
                                              const int* __restrict__ dst, int E) {
    int e = blockIdx.x * blockDim.x + threadIdx.x;
    if (e >= E) return;
    int d = dst[e];
    int pos = g_rowptr[d] + atomicAdd(&g_cur[d], 1);
    g_csri[pos] = src[e];
}

// ---------------- layer 1 front: xw' = dinv * (state @ W1); feat 160..191 ----------
__global__ void __launch_bounds__(256) k_xw0(const float* __restrict__ state,
                                             const float* __restrict__ W, int Nn) {
    __shared__ float Ws[1024];
    int tid = threadIdx.x;
    for (int i = tid; i < 1024; i += 256) Ws[i] = W[i];
    __syncthreads();
    int lane = tid & 31;
    int node = blockIdx.x * 8 + (tid >> 5);
    if (node >= Nn) return;
    float v = state[node * 32 + lane];
    __nv_bfloat16 h, l;
    bsplit(v, h, l);
    size_t o = (size_t)node * 192 + 160 + lane;
    g_fh[o] = h;
    g_fl[o] = l;
    float acc = 0.0f;
#pragma unroll
    for (int k = 0; k < 32; k++) {
        float xk = __shfl_sync(0xffffffffu, v, k);
        acc = fmaf(xk, Ws[k * 32 + lane], acc);
    }
    g_xwA[node * 32 + lane] = g_dinv[node] * acc;
}

// ---------------- fused pull layer (dinv pre-scaled) ----------
// out = relu(b + dinv_d * (xw'_d + sum_e xw'_src)); next xw' = dinv_d * (out @ Wnext)
template <int FCOL, int HASNEXT, int PP>
__global__ void __launch_bounds__(256) k_pull(const float* __restrict__ b_cur,
                                              const float* __restrict__ Wnext, int Nn) {
    const float* __restrict__ xw_in = PP ? g_xwB : g_xwA;
    float* __restrict__ xw_out      = PP ? g_xwA : g_xwB;
    __shared__ float Ws[1024];
    int tid = threadIdx.x;
    if (HASNEXT) {
        for (int i = tid; i < 1024; i += 256) Ws[i] = Wnext[i];
        __syncthreads();
    }
    int lane = tid & 31;
    int node = blockIdx.x * 8 + (tid >> 5);
    if (node >= Nn) return;

    float acc = xw_in[node * 32 + lane];
    int start = g_rowptr[node];
    int cnt = g_cnt[node];
    for (int e = 0; e < cnt; e++) {
        int s = g_csri[start + e];
        acc += xw_in[(size_t)s * 32 + lane];
    }
    float di = g_dinv[node];
    float v = fmaxf(fmaf(di, acc, b_cur[lane]), 0.0f);
    __nv_bfloat16 h, l;
    bsplit(v, h, l);
    size_t o = (size_t)node * 192 + FCOL + lane;
    g_fh[o] = h;
    g_fl[o] = l;
    if (HASNEXT) {
        float a2 = 0.0f;
#pragma unroll
        for (int k = 0; k < 32; k++) {
            float xk = __shfl_sync(0xffffffffu, v, k);
            a2 = fmaf(xk, Ws[k * 32 + lane], a2);
        }
        xw_out[node * 32 + lane] = di * a2;
    }
}

// ---------------- weight convert ----------------
template <int K, int WHICH>
__global__ void __launch_bounds__(256) k_convB(const float* __restrict__ Wt) {
    int idx = blockIdx.x * blockDim.x + threadIdx.x;
    if (idx >= K * 256) return;
    int k = idx >> 8, n = idx & 255;
    __nv_bfloat16 h, l;
    bsplit(Wt[idx], h, l);
    if (WHICH == 0) { g_B1h[n * K + k] = h; g_B1l[n * K + k] = l; }
    else           { g_B2h[n * K + k] = h; g_B2l[n * K + k] = l; }
}

// ---------------- wmma bf16x3 split GEMM, cp.async 2-stage pipeline ----------------
template <int KTOT, int SRC>
__global__ void __launch_bounds__(256) k_gemm_mma(const float* __restrict__ bias,
                                                  const float* __restrict__ W3, int Nn) {
    extern __shared__ char sm[];
    const int LDT = 40;
    const int STG = 40960;

    int tid = threadIdx.x;
    int wid = tid >> 5, lane = tid & 31;
    int wm = wid & 3, wn = wid >> 2;
    int m0 = blockIdx.x * 128;
    int n0 = blockIdx.y * 128;

    const __nv_bfloat16* gAh = (SRC == 0) ? g_fh : g_h1h;
    const __nv_bfloat16* gAl = (SRC == 0) ? g_fl : g_h1l;
    const __nv_bfloat16* gBh = (SRC == 0) ? g_B1h : g_B2h;
    const __nv_bfloat16* gBl = (SRC == 0) ? g_B1l : g_B2l;

    const int NCH = KTOT / 32;

    auto issue = [&](int ch, int stg) {
        int k0 = ch * 32;
        char* base = sm + stg * STG;
#pragma unroll
        for (int u = 0; u < 2; u++) {
            int idx = tid + u * 256;
            int r = idx >> 2, c = idx & 3;
            int gm = m0 + r; if (gm >= Nn) gm = Nn - 1;
            int gn = n0 + r;
            size_t ao = (size_t)gm * KTOT + k0 + c * 8;
            size_t bo = (size_t)gn * KTOT + k0 + c * 8;
            int so = r * (LDT * 2) + c * 16;
            cpasync16(base + so,          gAh + ao);
            cpasync16(base + 10240 + so,  gAl + ao);
            cpasync16(base + 20480 + so,  gBh + bo);
            cpasync16(base + 30720 + so,  gBl + bo);
        }
    };

    wmma::fragment<wmma::accumulator, 16, 16, 16, float> acc[2][4];
#pragma unroll
    for (int i = 0; i < 2; i++)
#pragma unroll
        for (int j = 0; j < 4; j++) wmma::fill_fragment(acc[i][j], 0.0f);

    issue(0, 0);
    CP_COMMIT();

    for (int ch = 0; ch < NCH; ch++) {
        if (ch + 1 < NCH) {
            issue(ch + 1, (ch + 1) & 1);
            CP_COMMIT();
            asm volatile("cp.async.wait_group 1;" ::: "memory");
        } else {
            asm volatile("cp.async.wait_group 0;" ::: "memory");
        }
        __syncthreads();

        char* base = sm + (ch & 1) * STG;
        __nv_bfloat16* Ah = (__nv_bfloat16*)(base);
        __nv_bfloat16* Al = (__nv_bfloat16*)(base + 10240);
        __nv_bfloat16* Bh = (__nv_bfloat16*)(base + 20480);
        __nv_bfloat16* Bl = (__nv_bfloat16*)(base + 30720);

#pragma unroll
        for (int kk = 0; kk < 2; kk++) {
            wmma::fragment<wmma::matrix_a, 16, 16, 16, __nv_bfloat16, wmma::row_major> fah[2], fal[2];
            wmma::fragment<wmma::matrix_b, 16, 16, 16, __nv_bfloat16, wmma::col_major> fbh[4], fbl[4];
#pragma unroll
            for (int i = 0; i < 2; i++) {
                wmma::load_matrix_sync(fah[i], Ah + (wm * 32 + i * 16) * LDT + kk * 16, LDT);
                wmma::load_matrix_sync(fal[i], Al + (wm * 32 + i * 16) * LDT + kk * 16, LDT);
            }
#pragma unroll
            for (int j = 0; j < 4; j++) {
                wmma::load_matrix_sync(fbh[j], Bh + (wn * 64 + j * 16) * LDT + kk * 16, LDT);
                wmma::load_matrix_sync(fbl[j], Bl + (wn * 64 + j * 16) * LDT + kk * 16, LDT);
            }
#pragma unroll
            for (int i = 0; i < 2; i++)
#pragma unroll
                for (int j = 0; j < 4; j++) {
                    wmma::mma_sync(acc[i][j], fah[i], fbh[j], acc[i][j]);
                    wmma::mma_sync(acc[i][j], fah[i], fbl[j], acc[i][j]);
                    wmma::mma_sync(acc[i][j], fal[i], fbh[j], acc[i][j]);
                }
        }
        __syncthreads();
    }

    float* stage = (float*)(sm + wid * 1280);
    const int LDS_ = 20;
    float dot[2] = {0.0f, 0.0f};
#pragma unroll
    for (int i = 0; i < 2; i++)
#pragma unroll
        for (int j = 0; j < 4; j++) {
            wmma::store_matrix_sync(stage, acc[i][j], LDS_, wmma::mem_row_major);
            __syncwarp();
            int r = lane >> 1;
            int c0 = (lane & 1) * 8;
            int gm = m0 + wm * 32 + i * 16 + r;
            int gn0 = n0 + wn * 64 + j * 16 + c0;
            if (gm < Nn) {
#pragma unroll
                for (int t = 0; t < 8; t++) {
                    float v = stage[r * LDS_ + c0 + t] + bias[gn0 + t];
                    v = v > 0.0f ? v : 0.01f * v;
                    if (SRC == 0) {
                        __nv_bfloat16 h, l;
                        bsplit(v, h, l);
                        g_h1h[(size_t)gm * 256 + gn0 + t] = h;
                        g_h1l[(size_t)gm * 256 + gn0 + t] = l;
                    } else {
                        dot[i] = fmaf(v, W3[gn0 + t], dot[i]);
                    }
                }
            }
            __syncwarp();
        }
    if (SRC == 1) {
        int cid = wn + 2 * blockIdx.y;
#pragma unroll
        for (int i = 0; i < 2; i++) {
            float s = dot[i] + __shfl_xor_sync(0xffffffffu, dot[i], 1);
            int gm = m0 + wm * 32 + i * 16 + (lane >> 1);
            if ((lane & 1) == 0 && gm < Nn) g_linpart[(size_t)gm * 4 + cid] = s;
        }
    }
}

// ---------------- fused softplus + first reduction pass ----------------
__global__ void __launch_bounds__(256) k_reduce1(const float* __restrict__ b3, int Nn) {
    __shared__ float sh[256];
    float s = 0.0f;
    for (int i = blockIdx.x * 256 + threadIdx.x; i < Nn; i += 256 * 512) {
        const float4 p = *(const float4*)(g_linpart + (size_t)i * 4);
        float x = ((p.x + p.y) + (p.z + p.w)) + b3[0];   // fixed order: deterministic
        float c = fmaxf(x, 0.0f) + log1pf(expf(-fabsf(x)));
        g_conc[i] = c;
        s += c;
    }
    sh[threadIdx.x] = s;
    __syncthreads();
    for (int o = 128; o; o >>= 1) {
        if (threadIdx.x < o) sh[threadIdx.x] += sh[threadIdx.x + o];
        __syncthreads();
    }
    if (threadIdx.x == 0) g_partial[blockIdx.x] = sh[0];
}
__global__ void __launch_bounds__(512) k_reduce2() {
    __shared__ float sh[512];
    sh[threadIdx.x] = g_partial[threadIdx.x];
    __syncthreads();
    for (int o = 256; o; o >>= 1) {
        if (threadIdx.x < o) sh[threadIdx.x] += sh[threadIdx.x + o];
        __syncthreads();
    }
    if (threadIdx.x == 0) g_sum = sh[0];
}
__global__ void __launch_bounds__(256) k_final(float* __restrict__ out, int Nn) {
    int i = blockIdx.x * blockDim.x + threadIdx.x;
    if (i < Nn) out[i] = g_conc[i] / (g_sum + 1e-20f);
}

// ---------------- launch ----------------
extern "C" void kernel_launch(void* const* d_in, const int* in_sizes, int n_in,
                              void* d_out, int out_size) {
    const float* state = (const float*)d_in[0];
    const int* ei = (const int*)d_in[1];
    const float* W1 = (const float*)d_in[2];
    const float* b1 = (const float*)d_in[3];
    const float* W2 = (const float*)d_in[4];
    const float* b2 = (const float*)d_in[5];
    const float* W3 = (const float*)d_in[6];
    const float* b3 = (const float*)d_in[7];
    const float* lW1 = (const float*)d_in[8];
    const float* lb1 = (const float*)d_in[9];
    const float* lW2 = (const float*)d_in[10];
    const float* lb2 = (const float*)d_in[11];
    const float* lW3 = (const float*)d_in[12];
    const float* lb3 = (const float*)d_in[13];

    int Nn = in_sizes[0] / 32;
    int E = in_sizes[1] / 2;
    const int* src = ei;
    const int* dst = ei + E;
    float* out = (float*)d_out;

    int gN = (Nn + 255) / 256;
    int gE = (E + 255) / 256;
    int gP = (Nn + 7) / 8;
    int nb = (Nn + 255) / 256;
    const int GEMM_SMEM = 81920;

    cudaFuncSetAttribute((const void*)k_gemm_mma<192, 0>,
                         cudaFuncAttributeMaxDynamicSharedMemorySize, GEMM_SMEM);
    cudaFuncSetAttribute((const void*)k_gemm_mma<256, 1>,
                         cudaFuncAttributeMaxDynamicSharedMemorySize, GEMM_SMEM);

    // CSR build
    k_prep<<<gN, 256>>>(Nn);
    k_cnt<<<gE, 256>>>(dst, E);
    k_scanA<<<nb, 256>>>(Nn);
    k_scanB<<<1, 512>>>(nb);
    k_scanC<<<nb, 256>>>(Nn);
    k_fill<<<gE, 256>>>(src, dst, E);
    k_convB<192, 0><<<(192 * 256 + 255) / 256, 256>>>(lW1);
    k_convB<256, 1><<<(256 * 256 + 255) / 256, 256>>>(lW2);

    // GCN stack
    k_xw0<<<gP, 256>>>(state, W1, Nn);
    k_pull<0,   1, 0><<<gP, 256>>>(b1, W2, Nn);
    k_pull<32,  1, 1><<<gP, 256>>>(b2, W3, Nn);
    k_pull<64,  1, 0><<<gP, 256>>>(b3, W3, Nn);
    k_pull<96,  1, 1><<<gP, 256>>>(b3, W3, Nn);
    k_pull<128, 0, 0><<<gP, 256>>>(b3, W3, Nn);

    dim3 gg((Nn + 127) / 128, 2);
    k_gemm_mma<192, 0><<<gg, 256, GEMM_SMEM>>>(lb1, lW3, Nn);
    k_gemm_mma<256, 1><<<gg, 256, GEMM_SMEM>>>(lb2, lW3, Nn);

    k_reduce1<<<512, 256>>>(lb3, Nn);
    k_reduce2<<<1, 512>>>();
    k_final<<<gN, 256>>>(out, Nn);
}

// round 17
// speedup vs baseline: 1.2662x; 1.0140x over previous
#include <cuda_runtime.h>
#include <cuda_bf16.h>
#include <mma.h>
#include <cstdint>

using namespace nvcuda;

#define MAXN 100000
#define MAXE 1600000

// ---------------- static scratch (allocation-free rule) ----------------
__device__ __align__(16) int   g_cnt[MAXN];
__device__ __align__(16) int   g_cur[MAXN];
__device__ __align__(16) int   g_rowptr[MAXN];
__device__ int g_total;
__device__ __align__(16) float g_dinv[MAXN];
__device__ __align__(16) int   g_csri[MAXE];     // src only (dinv pre-scaled xw)
__device__ __align__(16) float g_xwA[MAXN * 32];
__device__ __align__(16) float g_xwB[MAXN * 32];
__device__ __align__(16) __nv_bfloat16 g_fh[(size_t)MAXN * 192];
__device__ __align__(16) __nv_bfloat16 g_fl[(size_t)MAXN * 192];
__device__ __align__(16) __nv_bfloat16 g_h1h[(size_t)MAXN * 256];
__device__ __align__(16) __nv_bfloat16 g_h1l[(size_t)MAXN * 256];
__device__ __align__(16) float g_linpart[(size_t)MAXN * 4];
__device__ __align__(16) __nv_bfloat16 g_B1h[192 * 256];
__device__ __align__(16) __nv_bfloat16 g_B1l[192 * 256];
__device__ __align__(16) __nv_bfloat16 g_B2h[256 * 256];
__device__ __align__(16) __nv_bfloat16 g_B2l[256 * 256];
__device__ __align__(16) float g_conc[MAXN];
__device__ float g_partial[512];

__device__ __forceinline__ void bsplit(float v, __nv_bfloat16& h, __nv_bfloat16& l) {
    h = __float2bfloat16(v);
    l = __float2bfloat16(v - __bfloat162float(h));
}
__device__ __forceinline__ void cpasync16(void* dst_smem, const void* src) {
    uint32_t d = (uint32_t)__cvta_generic_to_shared(dst_smem);
    asm volatile("cp.async.cg.shared.global [%0], [%1], 16;" :: "r"(d), "l"(src));
}
#define CP_COMMIT() asm volatile("cp.async.commit_group;" ::: "memory")

// ---------------- CSR build ----------------
__global__ void __launch_bounds__(256) k_prep(int Nn) {
    int i = blockIdx.x * blockDim.x + threadIdx.x;
    if (i < Nn) { g_cnt[i] = 0; g_cur[i] = 0; }
    if (i == 0) g_total = 0;
}
__global__ void __launch_bounds__(256) k_cnt(const int* __restrict__ dst, int E) {
    int e = blockIdx.x * blockDim.x + threadIdx.x;
    if (e < E) atomicAdd(&g_cnt[dst[e]], 1);
}
// atomic bump allocation of rowptr + dinv (replaces 3-kernel scan)
__global__ void __launch_bounds__(256) k_alloc(int Nn) {
    int i = blockIdx.x * blockDim.x + threadIdx.x;
    if (i >= Nn) return;
    int c = g_cnt[i];
    g_rowptr[i] = atomicAdd(&g_total, c);
    g_dinv[i] = rsqrtf((float)(c + 1));
}
__global__ void __launch_bounds__(256) k_fill(const int* __restrict__ src,
                                              const int* __restrict__ dst, int E) {
    int e = blockIdx.x * blockDim.x + threadIdx.x;
    if (e >= E) return;
    int d = dst[e];
    int pos = g_rowptr[d] + atomicAdd(&g_cur[d], 1);
    g_csri[pos] = src[e];
}

// ---------------- layer 1 front: xw' = dinv * (state @ W1); feat 160..191 ----------
__global__ void __launch_bounds__(256) k_xw0(const float* __restrict__ state,
                                             const float* __restrict__ W, int Nn) {
    __shared__ float Ws[1024];
    int tid = threadIdx.x;
    for (int i = tid; i < 1024; i += 256) Ws[i] = W[i];
    __syncthreads();
    int lane = tid & 31;
    int node = blockIdx.x * 8 + (tid >> 5);
    if (node >= Nn) return;
    float v = state[node * 32 + lane];
    __nv_bfloat16 h, l;
    bsplit(v, h, l);
    size_t o = (size_t)node * 192 + 160 + lane;
    g_fh[o] = h;
    g_fl[o] = l;
    float acc = 0.0f;
#pragma unroll
    for (int k = 0; k < 32; k++) {
        float xk = __shfl_sync(0xffffffffu, v, k);
        acc = fmaf(xk, Ws[k * 32 + lane], acc);
    }
    g_xwA[node * 32 + lane] = g_dinv[node] * acc;
}

// ---------------- fused pull layer (dinv pre-scaled) ----------
template <int FCOL, int HASNEXT, int PP>
__global__ void __launch_bounds__(256) k_pull(const float* __restrict__ b_cur,
                                              const float* __restrict__ Wnext, int Nn) {
    const float* __restrict__ xw_in = PP ? g_xwB : g_xwA;
    float* __restrict__ xw_out      = PP ? g_xwA : g_xwB;
    __shared__ float Ws[1024];
    int tid = threadIdx.x;
    if (HASNEXT) {
        for (int i = tid; i < 1024; i += 256) Ws[i] = Wnext[i];
        __syncthreads();
    }
    int lane = tid & 31;
    int node = blockIdx.x * 8 + (tid >> 5);
    if (node >= Nn) return;

    float acc = xw_in[node * 32 + lane];
    int start = g_rowptr[node];
    int cnt = g_cnt[node];
    for (int e = 0; e < cnt; e++) {
        int s = g_csri[start + e];
        acc += xw_in[(size_t)s * 32 + lane];
    }
    float di = g_dinv[node];
    float v = fmaxf(fmaf(di, acc, b_cur[lane]), 0.0f);
    __nv_bfloat16 h, l;
    bsplit(v, h, l);
    size_t o = (size_t)node * 192 + FCOL + lane;
    g_fh[o] = h;
    g_fl[o] = l;
    if (HASNEXT) {
        float a2 = 0.0f;
#pragma unroll
        for (int k = 0; k < 32; k++) {
            float xk = __shfl_sync(0xffffffffu, v, k);
            a2 = fmaf(xk, Ws[k * 32 + lane], a2);
        }
        xw_out[node * 32 + lane] = di * a2;
    }
}

// ---------------- weight convert (both matrices, one launch) ----------------
__global__ void __launch_bounds__(256) k_convB(const float* __restrict__ W1t,
                                               const float* __restrict__ W2t) {
    int idx = blockIdx.x * blockDim.x + threadIdx.x;
    const int N1 = 192 * 256;
    if (idx < N1) {
        int k = idx >> 8, n = idx & 255;
        __nv_bfloat16 h, l;
        bsplit(W1t[idx], h, l);
        g_B1h[n * 192 + k] = h;
        g_B1l[n * 192 + k] = l;
    } else {
        int j = idx - N1;
        if (j >= 256 * 256) return;
        int k = j >> 8, n = j & 255;
        __nv_bfloat16 h, l;
        bsplit(W2t[j], h, l);
        g_B2h[n * 256 + k] = h;
        g_B2l[n * 256 + k] = l;
    }
}

// ---------------- wmma bf16x3 split GEMM, cp.async 2-stage pipeline ----------------
template <int KTOT, int SRC>
__global__ void __launch_bounds__(256) k_gemm_mma(const float* __restrict__ bias,
                                                  const float* __restrict__ W3, int Nn) {
    extern __shared__ char sm[];
    const int LDT = 40;
    const int STG = 40960;

    int tid = threadIdx.x;
    int wid = tid >> 5, lane = tid & 31;
    int wm = wid & 3, wn = wid >> 2;
    int m0 = blockIdx.x * 128;
    int n0 = blockIdx.y * 128;

    const __nv_bfloat16* gAh = (SRC == 0) ? g_fh : g_h1h;
    const __nv_bfloat16* gAl = (SRC == 0) ? g_fl : g_h1l;
    const __nv_bfloat16* gBh = (SRC == 0) ? g_B1h : g_B2h;
    const __nv_bfloat16* gBl = (SRC == 0) ? g_B1l : g_B2l;

    const int NCH = KTOT / 32;

    auto issue = [&](int ch, int stg) {
        int k0 = ch * 32;
        char* base = sm + stg * STG;
#pragma unroll
        for (int u = 0; u < 2; u++) {
            int idx = tid + u * 256;
            int r = idx >> 2, c = idx & 3;
            int gm = m0 + r; if (gm >= Nn) gm = Nn - 1;
            int gn = n0 + r;
            size_t ao = (size_t)gm * KTOT + k0 + c * 8;
            size_t bo = (size_t)gn * KTOT + k0 + c * 8;
            int so = r * (LDT * 2) + c * 16;
            cpasync16(base + so,          gAh + ao);
            cpasync16(base + 10240 + so,  gAl + ao);
            cpasync16(base + 20480 + so,  gBh + bo);
            cpasync16(base + 30720 + so,  gBl + bo);
        }
    };

    wmma::fragment<wmma::accumulator, 16, 16, 16, float> acc[2][4];
#pragma unroll
    for (int i = 0; i < 2; i++)
#pragma unroll
        for (int j = 0; j < 4; j++) wmma::fill_fragment(acc[i][j], 0.0f);

    issue(0, 0);
    CP_COMMIT();

    for (int ch = 0; ch < NCH; ch++) {
        if (ch + 1 < NCH) {
            issue(ch + 1, (ch + 1) & 1);
            CP_COMMIT();
            asm volatile("cp.async.wait_group 1;" ::: "memory");
        } else {
            asm volatile("cp.async.wait_group 0;" ::: "memory");
        }
        __syncthreads();

        char* base = sm + (ch & 1) * STG;
        __nv_bfloat16* Ah = (__nv_bfloat16*)(base);
        __nv_bfloat16* Al = (__nv_bfloat16*)(base + 10240);
        __nv_bfloat16* Bh = (__nv_bfloat16*)(base + 20480);
        __nv_bfloat16* Bl = (__nv_bfloat16*)(base + 30720);

#pragma unroll
        for (int kk = 0; kk < 2; kk++) {
            wmma::fragment<wmma::matrix_a, 16, 16, 16, __nv_bfloat16, wmma::row_major> fah[2], fal[2];
            wmma::fragment<wmma::matrix_b, 16, 16, 16, __nv_bfloat16, wmma::col_major> fbh[4], fbl[4];
#pragma unroll
            for (int i = 0; i < 2; i++) {
                wmma::load_matrix_sync(fah[i], Ah + (wm * 32 + i * 16) * LDT + kk * 16, LDT);
                wmma::load_matrix_sync(fal[i], Al + (wm * 32 + i * 16) * LDT + kk * 16, LDT);
            }
#pragma unroll
            for (int j = 0; j < 4; j++) {
                wmma::load_matrix_sync(fbh[j], Bh + (wn * 64 + j * 16) * LDT + kk * 16, LDT);
                wmma::load_matrix_sync(fbl[j], Bl + (wn * 64 + j * 16) * LDT + kk * 16, LDT);
            }
#pragma unroll
            for (int i = 0; i < 2; i++)
#pragma unroll
                for (int j = 0; j < 4; j++) {
                    wmma::mma_sync(acc[i][j], fah[i], fbh[j], acc[i][j]);
                    wmma::mma_sync(acc[i][j], fah[i], fbl[j], acc[i][j]);
                    wmma::mma_sync(acc[i][j], fal[i], fbh[j], acc[i][j]);
                }
        }
        __syncthreads();
    }

    float* stage = (float*)(sm + wid * 1280);
    const int LDS_ = 20;
    float dot[2] = {0.0f, 0.0f};
#pragma unroll
    for (int i = 0; i < 2; i++)
#pragma unroll
        for (int j = 0; j < 4; j++) {
            wmma::store_matrix_sync(stage, acc[i][j], LDS_, wmma::mem_row_major);
            __syncwarp();
            int r = lane >> 1;
            int c0 = (lane & 1) * 8;
            int gm = m0 + wm * 32 + i * 16 + r;
            int gn0 = n0 + wn * 64 + j * 16 + c0;
            if (gm < Nn) {
#pragma unroll
                for (int t = 0; t < 8; t++) {
                    float v = stage[r * LDS_ + c0 + t] + bias[gn0 + t];
                    v = v > 0.0f ? v : 0.01f * v;
                    if (SRC == 0) {
                        __nv_bfloat16 h, l;
                        bsplit(v, h, l);
                        g_h1h[(size_t)gm * 256 + gn0 + t] = h;
                        g_h1l[(size_t)gm * 256 + gn0 + t] = l;
                    } else {
                        dot[i] = fmaf(v, W3[gn0 + t], dot[i]);
                    }
                }
            }
            __syncwarp();
        }
    if (SRC == 1) {
        int cid = wn + 2 * blockIdx.y;
#pragma unroll
        for (int i = 0; i < 2; i++) {
            float s = dot[i] + __shfl_xor_sync(0xffffffffu, dot[i], 1);
            int gm = m0 + wm * 32 + i * 16 + (lane >> 1);
            if ((lane & 1) == 0 && gm < Nn) g_linpart[(size_t)gm * 4 + cid] = s;
        }
    }
}

// ---------------- fused softplus + first reduction pass ----------------
__global__ void __launch_bounds__(256) k_reduce1(const float* __restrict__ b3, int Nn) {
    __shared__ float sh[256];
    float s = 0.0f;
    for (int i = blockIdx.x * 256 + threadIdx.x; i < Nn; i += 256 * 512) {
        const float4 p = *(const float4*)(g_linpart + (size_t)i * 4);
        float x = ((p.x + p.y) + (p.z + p.w)) + b3[0];
        float c = fmaxf(x, 0.0f) + log1pf(expf(-fabsf(x)));
        g_conc[i] = c;
        s += c;
    }
    sh[threadIdx.x] = s;
    __syncthreads();
    for (int o = 128; o; o >>= 1) {
        if (threadIdx.x < o) sh[threadIdx.x] += sh[threadIdx.x + o];
        __syncthreads();
    }
    if (threadIdx.x == 0) g_partial[blockIdx.x] = sh[0];
}
// final: each block redundantly reduces the 512 partials (fixed order ->
// identical value in every block, deterministic), then normalizes its slice.
__global__ void __launch_bounds__(256) k_final(float* __restrict__ out, int Nn) {
    __shared__ float sh[256];
    int t = threadIdx.x;
    sh[t] = g_partial[t] + g_partial[t + 256];
    __syncthreads();
    for (int o = 128; o; o >>= 1) {
        if (t < o) sh[t] += sh[t + o];
        __syncthreads();
    }
    float inv = 1.0f / (sh[0] + 1e-20f);
    int i = blockIdx.x * blockDim.x + t;
    if (i < Nn) out[i] = g_conc[i] * inv;
}

// ---------------- launch ----------------
extern "C" void kernel_launch(void* const* d_in, const int* in_sizes, int n_in,
                              void* d_out, int out_size) {
    const float* state = (const float*)d_in[0];
    const int* ei = (const int*)d_in[1];
    const float* W1 = (const float*)d_in[2];
    const float* b1 = (const float*)d_in[3];
    const float* W2 = (const float*)d_in[4];
    const float* b2 = (const float*)d_in[5];
    const float* W3 = (const float*)d_in[6];
    const float* b3 = (const float*)d_in[7];
    const float* lW1 = (const float*)d_in[8];
    const float* lb1 = (const float*)d_in[9];
    const float* lW2 = (const float*)d_in[10];
    const float* lb2 = (const float*)d_in[11];
    const float* lW3 = (const float*)d_in[12];
    const float* lb3 = (const float*)d_in[13];

    int Nn = in_sizes[0] / 32;
    int E = in_sizes[1] / 2;
    const int* src = ei;
    const int* dst = ei + E;
    float* out = (float*)d_out;

    int gN = (Nn + 255) / 256;
    int gE = (E + 255) / 256;
    int gP = (Nn + 7) / 8;
    const int GEMM_SMEM = 81920;

    cudaFuncSetAttribute((const void*)k_gemm_mma<192, 0>,
                         cudaFuncAttributeMaxDynamicSharedMemorySize, GEMM_SMEM);
    cudaFuncSetAttribute((const void*)k_gemm_mma<256, 1>,
                         cudaFuncAttributeMaxDynamicSharedMemorySize, GEMM_SMEM);

    // CSR build
    k_prep<<<gN, 256>>>(Nn);
    k_cnt<<<gE, 256>>>(dst, E);
    k_alloc<<<gN, 256>>>(Nn);
    k_fill<<<gE, 256>>>(src, dst, E);
    k_convB<<<(192 * 256 + 256 * 256 + 255) / 256, 256>>>(lW1, lW2);

    // GCN stack
    k_xw0<<<gP, 256>>>(state, W1, Nn);
    k_pull<0,   1, 0><<<gP, 256>>>(b1, W2, Nn);
    k_pull<32,  1, 1><<<gP, 256>>>(b2, W3, Nn);
    k_pull<64,  1, 0><<<gP, 256>>>(b3, W3, Nn);
    k_pull<96,  1, 1><<<gP, 256>>>(b3, W3, Nn);
    k_pull<128, 0, 0><<<gP, 256>>>(b3, W3, Nn);

    dim3 gg((Nn + 127) / 128, 2);
    k_gemm_mma<192, 0><<<gg, 256, GEMM_SMEM>>>(lb1, lW3, Nn);
    k_gemm_mma<256, 1><<<gg, 256, GEMM_SMEM>>>(lb2, lW3, Nn);

    k_reduce1<<<512, 256>>>(lb3, Nn);
    k_final<<<gN, 256>>>(out, Nn);
}